// round 1
// baseline (speedup 1.0000x reference)
#include <cuda_runtime.h>
#include <math.h>

#define F_IN    128
#define HEADS   4
#define CDIM    64
#define HC      256      // HEADS*CDIM
#define HIDDEN  128
#define MAXN    50000
#define MAXG    1000
#define CAP     1024     // per-target edge bin capacity (mean deg ~17)
#define NEG_SLOPE 0.2f

// ---------------- scratch (static device globals; no allocation) ----------------
__device__ int   g_tgt_of_node[MAXN];
__device__ int   g_need_flag[MAXN];
__device__ int   g_need_slot[MAXN];
__device__ int   g_needed_nodes[MAXN];
__device__ int   g_num_needed;
__device__ int   g_tgt_node[MAXG];
__device__ int   g_deg[MAXG];
__device__ int   g_ce_src[MAXG * CAP];          // 4 MB: source NODE ids per target
__device__ float g_h[(size_t)MAXN * HC];        // 51.2 MB compacted h rows
__device__ float g_asrc[MAXN * HEADS];
__device__ float g_adst[MAXN * HEADS];

// ---------------- helpers ----------------
__device__ __forceinline__ void mark_needed(int node) {
    if (atomicCAS(&g_need_flag[node], 0, 1) == 0) {
        int s = atomicAdd(&g_num_needed, 1);
        g_need_slot[node] = s;
        g_needed_nodes[s] = node;
    }
}

__device__ __forceinline__ unsigned fenc(float f) {
    unsigned u = __float_as_uint(f);
    return (u & 0x80000000u) ? ~u : (u | 0x80000000u);
}
__device__ __forceinline__ float fdec(unsigned u) {
    return __uint_as_float((u & 0x80000000u) ? (u ^ 0x80000000u) : ~u);
}

// ---------------- K1: reset scratch ----------------
__global__ void k_init(int N, int G) {
    int i = blockIdx.x * blockDim.x + threadIdx.x;
    if (i < N) { g_tgt_of_node[i] = -1; g_need_flag[i] = 0; }
    if (i < G) g_deg[i] = 0;
    if (i == 0) g_num_needed = 0;
}

// ---------------- K2: mark target nodes ----------------
__global__ void k_targets(const int* __restrict__ ptr,
                          const int* __restrict__ tni, int G) {
    int g = blockIdx.x * blockDim.x + threadIdx.x;
    if (g >= G) return;
    int node = ptr[g] + tni[g];
    g_tgt_of_node[node] = g;
    g_tgt_node[g] = node;
    mark_needed(node);
}

// ---------------- K3: single edge scan -> bin edges per target, flag sources ----
__global__ void k_edges(const int* __restrict__ ei, int E, int G) {
    int i = blockIdx.x * blockDim.x + threadIdx.x;
    if (i >= E + G) return;
    int src, dst;
    if (i < E) { src = ei[i]; dst = ei[E + i]; }
    else       { src = g_tgt_node[i - E]; dst = src; }   // self loop for target
    int t = g_tgt_of_node[dst];
    if (t < 0) return;
    int pos = atomicAdd(&g_deg[t], 1);
    if (pos < CAP) g_ce_src[t * CAP + pos] = src;
    mark_needed(src);
}

// ---------------- K4: gathered GEMM  h[slot] = x[node] @ W  -------------------
// block: 256 threads (one per output channel), NT nodes per block
#define NT 16
__global__ void k_h(const float* __restrict__ x, const float* __restrict__ W) {
    __shared__ float xs[NT][F_IN];
    int base = blockIdx.x * NT;
    int nn = g_num_needed;
    if (base >= nn) return;
    int cnt = min(NT, nn - base);
    for (int i = threadIdx.x; i < cnt * F_IN; i += 256) {
        int m = i >> 7, k = i & 127;
        xs[m][k] = x[(size_t)g_needed_nodes[base + m] * F_IN + k];
    }
    __syncthreads();
    int j = threadIdx.x;                     // output channel 0..255
    float acc[NT];
    #pragma unroll
    for (int m = 0; m < NT; m++) acc[m] = 0.f;
    for (int k = 0; k < F_IN; k++) {
        float w = W[k * HC + j];
        #pragma unroll
        for (int m = 0; m < NT; m++) acc[m] += xs[m][k] * w;
    }
    for (int m = 0; m < cnt; m++)
        g_h[(size_t)(base + m) * HC + j] = acc[m];
}

// ---------------- K5: per-slot attention logits a_src, a_dst ------------------
__global__ void k_att(const float* __restrict__ att_src,
                      const float* __restrict__ att_dst) {
    int warps_per_blk = blockDim.x >> 5;
    int slot = blockIdx.x * warps_per_blk + (threadIdx.x >> 5);
    if (slot >= g_num_needed) return;
    int lane = threadIdx.x & 31;
    const float* hrow = &g_h[(size_t)slot * HC];
    #pragma unroll
    for (int head = 0; head < HEADS; head++) {
        float s = 0.f, d = 0.f;
        #pragma unroll
        for (int c = lane; c < CDIM; c += 32) {
            float hv = hrow[head * CDIM + c];
            s += hv * att_src[head * CDIM + c];
            d += hv * att_dst[head * CDIM + c];
        }
        #pragma unroll
        for (int o = 16; o > 0; o >>= 1) {
            s += __shfl_down_sync(0xFFFFFFFFu, s, o);
            d += __shfl_down_sync(0xFFFFFFFFu, d, o);
        }
        if (lane == 0) {
            g_asrc[slot * HEADS + head] = s;
            g_adst[slot * HEADS + head] = d;
        }
    }
}

// ---------------- K6: per-target softmax + aggregation + FC -------------------
#define CHUNK 64
__global__ void k_agg(const float* __restrict__ bias,
                      const float* __restrict__ fcW,
                      const float* __restrict__ fcb,
                      float* __restrict__ out) {
    int t = blockIdx.x;
    int tid = threadIdx.x;                       // blockDim = 256
    __shared__ float    s_adst[HEADS];
    __shared__ unsigned s_maxenc[HEADS];
    __shared__ float    s_max[HEADS], s_sum[HEADS];
    __shared__ float    s_acc[HC];
    __shared__ float    s_o[CDIM];
    __shared__ int      s_slot[CHUNK];
    __shared__ float    s_alpha[CHUNK][HEADS];

    int deg = min(g_deg[t], CAP);
    int tslot = g_need_slot[g_tgt_node[t]];
    if (tid < HEADS) {
        s_adst[tid] = g_adst[tslot * HEADS + tid];
        s_maxenc[tid] = 0u;
        s_sum[tid] = 0.f;
    }
    s_acc[tid] = 0.f;
    __syncthreads();

    // pass 1: per-head max of leaky_relu(a_src + a_dst)
    float lmax[HEADS] = {-INFINITY, -INFINITY, -INFINITY, -INFINITY};
    for (int e = tid; e < deg; e += 256) {
        int slot = g_need_slot[g_ce_src[t * CAP + e]];
        #pragma unroll
        for (int h = 0; h < HEADS; h++) {
            float v = g_asrc[slot * HEADS + h] + s_adst[h];
            v = (v > 0.f) ? v : NEG_SLOPE * v;
            lmax[h] = fmaxf(lmax[h], v);
        }
    }
    #pragma unroll
    for (int h = 0; h < HEADS; h++)
        atomicMax(&s_maxenc[h], fenc(lmax[h]));
    __syncthreads();
    if (tid < HEADS) s_max[tid] = fdec(s_maxenc[tid]);
    __syncthreads();

    // pass 2: per-head sum of exp(v - max)
    float lsum[HEADS] = {0.f, 0.f, 0.f, 0.f};
    for (int e = tid; e < deg; e += 256) {
        int slot = g_need_slot[g_ce_src[t * CAP + e]];
        #pragma unroll
        for (int h = 0; h < HEADS; h++) {
            float v = g_asrc[slot * HEADS + h] + s_adst[h];
            v = (v > 0.f) ? v : NEG_SLOPE * v;
            lsum[h] += expf(v - s_max[h]);
        }
    }
    #pragma unroll
    for (int h = 0; h < HEADS; h++)
        if (lsum[h] != 0.f) atomicAdd(&s_sum[h], lsum[h]);
    __syncthreads();

    // pass 3: weighted message accumulation, chunked
    int head = tid >> 6;                          // channel tid = head*64 + c
    float acc = 0.f;
    for (int base = 0; base < deg; base += CHUNK) {
        int n = min(CHUNK, deg - base);
        if (tid < n) {
            int slot = g_need_slot[g_ce_src[t * CAP + base + tid]];
            s_slot[tid] = slot;
            #pragma unroll
            for (int h = 0; h < HEADS; h++) {
                float v = g_asrc[slot * HEADS + h] + s_adst[h];
                v = (v > 0.f) ? v : NEG_SLOPE * v;
                s_alpha[tid][h] = expf(v - s_max[h]) / (s_sum[h] + 1e-16f);
            }
        }
        __syncthreads();
        for (int i = 0; i < n; i++)
            acc += s_alpha[i][head] * g_h[(size_t)s_slot[i] * HC + tid];
        __syncthreads();
    }
    s_acc[tid] = acc;
    __syncthreads();

    // mean over heads + bias
    if (tid < CDIM) {
        float o = (s_acc[tid] + s_acc[CDIM + tid] +
                   s_acc[2 * CDIM + tid] + s_acc[3 * CDIM + tid]) * 0.25f
                  + bias[tid];
        s_o[tid] = o;
    }
    __syncthreads();

    // fused FC: [64] @ [64,128] + b
    if (tid < HIDDEN) {
        float r = fcb[tid];
        #pragma unroll
        for (int c = 0; c < CDIM; c++)
            r += s_o[c] * fcW[c * HIDDEN + tid];
        out[(size_t)t * HIDDEN + tid] = r;
    }
}

// ---------------- launch ----------------
extern "C" void kernel_launch(void* const* d_in, const int* in_sizes, int n_in,
                              void* d_out, int out_size) {
    const float* x        = (const float*)d_in[0];
    const float* W        = (const float*)d_in[1];
    const float* att_src  = (const float*)d_in[2];
    const float* att_dst  = (const float*)d_in[3];
    const float* bias     = (const float*)d_in[4];
    const float* fc_W     = (const float*)d_in[5];
    const float* fc_b     = (const float*)d_in[6];
    const int*   ei       = (const int*)d_in[7];
    const int*   ptr      = (const int*)d_in[8];
    const int*   tni      = (const int*)d_in[9];
    float*       out      = (float*)d_out;

    int N = in_sizes[0] / F_IN;        // 50000
    int E = in_sizes[7] / 2;           // 800000
    int G = in_sizes[9];               // 1000

    k_init<<<(N + 255) / 256, 256>>>(N, G);
    k_targets<<<(G + 255) / 256, 256>>>(ptr, tni, G);
    k_edges<<<(E + G + 255) / 256, 256>>>(ei, E, G);
    k_h<<<(N + NT - 1) / NT, 256>>>(x, W);          // blocks past g_num_needed exit
    k_att<<<(N + 7) / 8, 256>>>(att_src, att_dst);  // 8 warps/block, guard inside
    k_agg<<<G, 256>>>(bias, fc_W, fc_b, out);
}

// round 2
// speedup vs baseline: 1.4049x; 1.4049x over previous
#include <cuda_runtime.h>
#include <math.h>

#define F_IN    128
#define HEADS   4
#define CDIM    64
#define HC      256      // HEADS*CDIM
#define HIDDEN  128
#define MAXN    50000
#define MAXG    1000
#define CAP     1024     // per-target edge bin capacity (mean deg ~17)
#define NEG_SLOPE 0.2f

// ---------------- scratch (static device globals; no allocation) ----------------
__device__ int   g_tgt_of_node[MAXN];
__device__ int   g_need_flag[MAXN];
__device__ int   g_need_slot[MAXN];
__device__ int   g_needed_nodes[MAXN];
__device__ int   g_num_needed;
__device__ int   g_tgt_node[MAXG];
__device__ int   g_deg[MAXG];
__device__ int   g_ce_src[MAXG * CAP];
__device__ float g_h[(size_t)MAXN * HC];
__device__ float g_asrc[MAXN * HEADS];
__device__ float g_adst[MAXN * HEADS];

// ---------------- helpers ----------------
__device__ __forceinline__ void mark_needed(int node) {
    if (atomicCAS(&g_need_flag[node], 0, 1) == 0) {
        int s = atomicAdd(&g_num_needed, 1);
        g_need_slot[node] = s;
        g_needed_nodes[s] = node;
    }
}

__device__ __forceinline__ unsigned fenc(float f) {
    unsigned u = __float_as_uint(f);
    return (u & 0x80000000u) ? ~u : (u | 0x80000000u);
}
__device__ __forceinline__ float fdec(unsigned u) {
    return __uint_as_float((u & 0x80000000u) ? (u ^ 0x80000000u) : ~u);
}

__device__ __forceinline__ unsigned to_tf32(float f) {
    unsigned r;
    asm("cvt.rna.tf32.f32 %0, %1;" : "=r"(r) : "f"(f));
    return r;
}

__device__ __forceinline__ void mma_tf32(float d[4],
                                         unsigned a0, unsigned a1, unsigned a2, unsigned a3,
                                         unsigned b0, unsigned b1) {
    asm("mma.sync.aligned.m16n8k8.row.col.f32.tf32.tf32.f32 "
        "{%0,%1,%2,%3},{%4,%5,%6,%7},{%8,%9},{%0,%1,%2,%3};"
        : "+f"(d[0]), "+f"(d[1]), "+f"(d[2]), "+f"(d[3])
        : "r"(a0), "r"(a1), "r"(a2), "r"(a3), "r"(b0), "r"(b1));
}

// ---------------- K1: reset scratch ----------------
__global__ void k_init(int N, int G) {
    int i = blockIdx.x * blockDim.x + threadIdx.x;
    if (i < N) { g_tgt_of_node[i] = -1; g_need_flag[i] = 0; }
    if (i < G) g_deg[i] = 0;
    if (i == 0) g_num_needed = 0;
}

// ---------------- K2: mark target nodes ----------------
__global__ void k_targets(const int* __restrict__ ptr,
                          const int* __restrict__ tni, int G) {
    int g = blockIdx.x * blockDim.x + threadIdx.x;
    if (g >= G) return;
    int node = ptr[g] + tni[g];
    g_tgt_of_node[node] = g;
    g_tgt_node[g] = node;
    mark_needed(node);
}

// ---------------- K3: edge scan -> bin edges per target, flag sources --------
__global__ void k_edges(const int* __restrict__ ei, int E, int G) {
    int i = blockIdx.x * blockDim.x + threadIdx.x;
    if (i >= E + G) return;
    int src, dst;
    if (i < E) { src = ei[i]; dst = ei[E + i]; }
    else       { src = g_tgt_node[i - E]; dst = src; }   // self loop for target
    int t = g_tgt_of_node[dst];
    if (t < 0) return;
    int pos = atomicAdd(&g_deg[t], 1);
    if (pos < CAP) g_ce_src[t * CAP + pos] = src;
    mark_needed(src);
}

// ---------------- K4: 3xTF32 tensor-core GEMM + fused attention logits -------
// Block: 256 threads (8 warps), 64 gathered nodes x 256 channels.
// Warp w: row half = w>>2 (32 rows), head = w&3 (64 cols = 8 n-tiles of 8).
// C = A(rows x 128) * W(128 x 256) via mma.m16n8k8, 3xTF32 split for fp32 acc.
#define MT 64
#define PAD 132   // stride % 32 == 4 -> conflict-free A-frag LDS

__global__ __launch_bounds__(256, 2)
void k_h_mma(const float* __restrict__ x, const float* __restrict__ W,
             const float* __restrict__ att_src, const float* __restrict__ att_dst) {
    __shared__ __align__(16) float xs[MT][PAD];
    int base = blockIdx.x * MT;
    int nn = g_num_needed;
    if (base >= nn) return;
    int cnt = min(MT, nn - base);
    int tid = threadIdx.x;

    // gathered x rows -> shared (zero-pad missing rows), float4 granularity
    for (int i = tid; i < MT * 32; i += 256) {
        int m = i >> 5, q = i & 31;
        float4 v = make_float4(0.f, 0.f, 0.f, 0.f);
        if (m < cnt)
            v = __ldg((const float4*)(x + (size_t)g_needed_nodes[base + m] * F_IN) + q);
        *(float4*)&xs[m][q * 4] = v;
    }
    __syncthreads();

    int w = tid >> 5, lane = tid & 31;
    int mhalf = w >> 2;          // 0..1
    int head  = w & 3;           // n-base = head*64
    int lr = lane >> 2, lc = lane & 3;

    float acc[2][8][4];
    #pragma unroll
    for (int a = 0; a < 2; a++)
        #pragma unroll
        for (int b = 0; b < 8; b++)
            #pragma unroll
            for (int c = 0; c < 4; c++) acc[a][b][c] = 0.f;

    #pragma unroll 1
    for (int ks = 0; ks < 16; ks++) {
        int k0 = ks * 8;
        // A fragments (hi/lo) for 2 m-tiles
        unsigned ah[2][4], al[2][4];
        #pragma unroll
        for (int mt = 0; mt < 2; mt++) {
            int r0 = mhalf * 32 + mt * 16;
            #pragma unroll
            for (int q = 0; q < 4; q++) {
                int rr = r0 + lr + (q & 1) * 8;
                int kk = k0 + lc + (q >> 1) * 4;
                float a = xs[rr][kk];
                unsigned hi = to_tf32(a);
                unsigned lo = to_tf32(a - __uint_as_float(hi));
                ah[mt][q] = hi; al[mt][q] = lo;
            }
        }
        #pragma unroll
        for (int nt = 0; nt < 8; nt++) {
            int ncol = head * 64 + nt * 8 + lr;
            float b0f = W[(k0 + lc) * HC + ncol];
            float b1f = W[(k0 + lc + 4) * HC + ncol];
            unsigned bh0 = to_tf32(b0f);
            unsigned bl0 = to_tf32(b0f - __uint_as_float(bh0));
            unsigned bh1 = to_tf32(b1f);
            unsigned bl1 = to_tf32(b1f - __uint_as_float(bh1));
            #pragma unroll
            for (int mt = 0; mt < 2; mt++) {
                mma_tf32(acc[mt][nt], al[mt][0], al[mt][1], al[mt][2], al[mt][3], bh0, bh1);
                mma_tf32(acc[mt][nt], ah[mt][0], ah[mt][1], ah[mt][2], ah[mt][3], bl0, bl1);
                mma_tf32(acc[mt][nt], ah[mt][0], ah[mt][1], ah[mt][2], ah[mt][3], bh0, bh1);
            }
        }
    }

    // epilogue: store h + fused attention logits (a_src, a_dst)
    float sA[2][2] = {{0.f, 0.f}, {0.f, 0.f}};
    float sD[2][2] = {{0.f, 0.f}, {0.f, 0.f}};
    #pragma unroll
    for (int mt = 0; mt < 2; mt++) {
        int r0 = mhalf * 32 + mt * 16 + lr;    // rows for c0,c1
        int r1 = r0 + 8;                       // rows for c2,c3
        #pragma unroll
        for (int nt = 0; nt < 8; nt++) {
            int col = head * 64 + nt * 8 + lc * 2;
            float2 as2 = *(const float2*)&att_src[col];
            float2 ad2 = *(const float2*)&att_dst[col];
            float c0 = acc[mt][nt][0], c1 = acc[mt][nt][1];
            float c2 = acc[mt][nt][2], c3 = acc[mt][nt][3];
            if (r0 < cnt)
                *(float2*)&g_h[(size_t)(base + r0) * HC + col] = make_float2(c0, c1);
            if (r1 < cnt)
                *(float2*)&g_h[(size_t)(base + r1) * HC + col] = make_float2(c2, c3);
            sA[mt][0] += c0 * as2.x + c1 * as2.y;
            sA[mt][1] += c2 * as2.x + c3 * as2.y;
            sD[mt][0] += c0 * ad2.x + c1 * ad2.y;
            sD[mt][1] += c2 * ad2.x + c3 * ad2.y;
        }
    }
    // reduce over the 4 lanes of each quad (lanes differing in bits 0..1)
    #pragma unroll
    for (int mt = 0; mt < 2; mt++)
        #pragma unroll
        for (int hf = 0; hf < 2; hf++) {
            #pragma unroll
            for (int off = 1; off <= 2; off <<= 1) {
                sA[mt][hf] += __shfl_xor_sync(0xFFFFFFFFu, sA[mt][hf], off);
                sD[mt][hf] += __shfl_xor_sync(0xFFFFFFFFu, sD[mt][hf], off);
            }
        }
    if (lc == 0) {
        #pragma unroll
        for (int mt = 0; mt < 2; mt++)
            #pragma unroll
            for (int hf = 0; hf < 2; hf++) {
                int r = mhalf * 32 + mt * 16 + hf * 8 + lr;
                if (r < cnt) {
                    g_asrc[(base + r) * HEADS + head] = sA[mt][hf];
                    g_adst[(base + r) * HEADS + head] = sD[mt][hf];
                }
            }
    }
}

// ---------------- K6: per-target softmax + aggregation + FC -------------------
#define CHUNK 64
__global__ void k_agg(const float* __restrict__ bias,
                      const float* __restrict__ fcW,
                      const float* __restrict__ fcb,
                      float* __restrict__ out) {
    int t = blockIdx.x;
    int tid = threadIdx.x;                       // blockDim = 256
    __shared__ float    s_adst[HEADS];
    __shared__ unsigned s_maxenc[HEADS];
    __shared__ float    s_max[HEADS], s_sum[HEADS];
    __shared__ float    s_acc[HC];
    __shared__ float    s_o[CDIM];
    __shared__ int      s_slot[CHUNK];
    __shared__ float    s_alpha[CHUNK][HEADS];

    int deg = min(g_deg[t], CAP);
    int tslot = g_need_slot[g_tgt_node[t]];
    if (tid < HEADS) {
        s_adst[tid] = g_adst[tslot * HEADS + tid];
        s_maxenc[tid] = 0u;
        s_sum[tid] = 0.f;
    }
    s_acc[tid] = 0.f;
    __syncthreads();

    // pass 1: per-head max of leaky_relu(a_src + a_dst)
    float lmax[HEADS] = {-INFINITY, -INFINITY, -INFINITY, -INFINITY};
    for (int e = tid; e < deg; e += 256) {
        int slot = g_need_slot[g_ce_src[t * CAP + e]];
        #pragma unroll
        for (int h = 0; h < HEADS; h++) {
            float v = g_asrc[slot * HEADS + h] + s_adst[h];
            v = (v > 0.f) ? v : NEG_SLOPE * v;
            lmax[h] = fmaxf(lmax[h], v);
        }
    }
    #pragma unroll
    for (int h = 0; h < HEADS; h++)
        atomicMax(&s_maxenc[h], fenc(lmax[h]));
    __syncthreads();
    if (tid < HEADS) s_max[tid] = fdec(s_maxenc[tid]);
    __syncthreads();

    // pass 2: per-head sum of exp(v - max)
    float lsum[HEADS] = {0.f, 0.f, 0.f, 0.f};
    for (int e = tid; e < deg; e += 256) {
        int slot = g_need_slot[g_ce_src[t * CAP + e]];
        #pragma unroll
        for (int h = 0; h < HEADS; h++) {
            float v = g_asrc[slot * HEADS + h] + s_adst[h];
            v = (v > 0.f) ? v : NEG_SLOPE * v;
            lsum[h] += expf(v - s_max[h]);
        }
    }
    #pragma unroll
    for (int h = 0; h < HEADS; h++)
        if (lsum[h] != 0.f) atomicAdd(&s_sum[h], lsum[h]);
    __syncthreads();

    // pass 3: weighted message accumulation, chunked, 4-way ILP
    int head = tid >> 6;
    float acc = 0.f;
    for (int cbase = 0; cbase < deg; cbase += CHUNK) {
        int n = min(CHUNK, deg - cbase);
        if (tid < n) {
            int slot = g_need_slot[g_ce_src[t * CAP + cbase + tid]];
            s_slot[tid] = slot;
            #pragma unroll
            for (int h = 0; h < HEADS; h++) {
                float v = g_asrc[slot * HEADS + h] + s_adst[h];
                v = (v > 0.f) ? v : NEG_SLOPE * v;
                s_alpha[tid][h] = expf(v - s_max[h]) / (s_sum[h] + 1e-16f);
            }
        }
        __syncthreads();
        int i = 0;
        for (; i + 4 <= n; i += 4) {
            float v0 = g_h[(size_t)s_slot[i]     * HC + tid];
            float v1 = g_h[(size_t)s_slot[i + 1] * HC + tid];
            float v2 = g_h[(size_t)s_slot[i + 2] * HC + tid];
            float v3 = g_h[(size_t)s_slot[i + 3] * HC + tid];
            acc += s_alpha[i][head] * v0 + s_alpha[i + 1][head] * v1
                 + s_alpha[i + 2][head] * v2 + s_alpha[i + 3][head] * v3;
        }
        for (; i < n; i++)
            acc += s_alpha[i][head] * g_h[(size_t)s_slot[i] * HC + tid];
        __syncthreads();
    }
    s_acc[tid] = acc;
    __syncthreads();

    // mean over heads + bias
    if (tid < CDIM) {
        float o = (s_acc[tid] + s_acc[CDIM + tid] +
                   s_acc[2 * CDIM + tid] + s_acc[3 * CDIM + tid]) * 0.25f
                  + bias[tid];
        s_o[tid] = o;
    }
    __syncthreads();

    // fused FC: [64] @ [64,128] + b
    if (tid < HIDDEN) {
        float r = fcb[tid];
        #pragma unroll
        for (int c = 0; c < CDIM; c++)
            r += s_o[c] * fcW[c * HIDDEN + tid];
        out[(size_t)t * HIDDEN + tid] = r;
    }
}

// ---------------- launch ----------------
extern "C" void kernel_launch(void* const* d_in, const int* in_sizes, int n_in,
                              void* d_out, int out_size) {
    const float* x        = (const float*)d_in[0];
    const float* W        = (const float*)d_in[1];
    const float* att_src  = (const float*)d_in[2];
    const float* att_dst  = (const float*)d_in[3];
    const float* bias     = (const float*)d_in[4];
    const float* fc_W     = (const float*)d_in[5];
    const float* fc_b     = (const float*)d_in[6];
    const int*   ei       = (const int*)d_in[7];
    const int*   ptr      = (const int*)d_in[8];
    const int*   tni      = (const int*)d_in[9];
    float*       out      = (float*)d_out;

    int N = in_sizes[0] / F_IN;        // 50000
    int E = in_sizes[7] / 2;           // 800000
    int G = in_sizes[9];               // 1000

    k_init<<<(N + 255) / 256, 256>>>(N, G);
    k_targets<<<(G + 255) / 256, 256>>>(ptr, tni, G);
    k_edges<<<(E + G + 255) / 256, 256>>>(ei, E, G);
    k_h_mma<<<(N + MT - 1) / MT, 256>>>(x, W, att_src, att_dst);
    k_agg<<<G, 256>>>(bias, fc_W, fc_b, out);
}